// round 8
// baseline (speedup 1.0000x reference)
#include <cuda_runtime.h>
#include <cuda_bf16.h>
#include <cstdint>

#define N_NODES 50000
#define N_EDGES 800000
#define D_IN 128
#define N_HEADS 8
#define PER_HEAD 16
#define LEAKY_ALPHA 0.2f

// ---------------- static device scratch (no allocations allowed) ------------
__device__ float g_q[(size_t)N_NODES * 128];         // 25.6 MB
__device__ float g_k[(size_t)N_NODES * 128];         // 25.6 MB
__device__ int   g_count[N_NODES];                   // in-degree histogram
__device__ int   g_offset[N_NODES + 1];              // CSR row offsets
__device__ int   g_cursor[N_NODES];                  // scatter cursors
__device__ int   g_src_sorted[N_EDGES];              // src node per CSR slot

__device__ __forceinline__ float lrelu(float v) {
    return v > 0.0f ? v : LEAKY_ALPHA * v;
}

// ---------------- Kernel 1: Q/K GEMM, broadcast-weight layout ----------------
// The old 4x4 micro-kernel read 2 smem bytes per FMA -> crossbar capped fma at
// 50% (observed 48%). New layout: warp = 32 nodes (one per lane) x 8 columns.
// Weight reads are warp-UNIFORM (broadcast, ~free on the crossbar); x reads are
// one LDS.128 per lane per 4-d step with row stride 132 floats (banks (4l+d)%32
// conflict-free within LDS.128 8-lane phases). ~0.6 smem B/FMA.
// Block 256 = 8 warps x 8 cols = 64 cols; 32 nodes per block; 4 CTAs/SM.
#define GEMM_BLOCK 256
#define GEMM_TILE_N 32
#define COLS_PER_CHUNK 64
#define XS_STRIDE 132

__global__ void __launch_bounds__(GEMM_BLOCK, 4)
qk_gemm_kernel(const float* __restrict__ x,
               const float* __restrict__ wq, const float* __restrict__ bq,
               const float* __restrict__ wk, const float* __restrict__ bk) {
    extern __shared__ float smem[];
    float* ws = smem;                        // [128][64] = 8192 floats (32KB)
    float* xs = smem + 8192;                 // [32][132] = 4224 floats (16.5KB)
    float* bs = smem + 8192 + 4224;          // 64 floats

    const int t = threadIdx.x;
    const int col0 = blockIdx.y * COLS_PER_CHUNK;  // 0,64,128,192
    const bool is_q = (col0 < 128);
    const float* wsrc = is_q ? wq : wk;
    const float* bsrc = is_q ? bq : bk;
    const int wcol0 = is_q ? col0 : (col0 - 128);

    // load weight chunk W[d][wcol0+c] (coalesced)
    for (int i = t; i < 128 * COLS_PER_CHUNK; i += GEMM_BLOCK) {
        int d = i >> 6, c = i & 63;
        ws[i] = wsrc[d * 128 + wcol0 + c];
    }
    if (t < COLS_PER_CHUNK) bs[t] = bsrc[wcol0 + t];

    // load x tile: 32 nodes x 128 floats, float4-coalesced, zero-fill past end
    const int n_base = blockIdx.x * GEMM_TILE_N;
    for (int i = t; i < GEMM_TILE_N * 32; i += GEMM_BLOCK) {
        int n = i >> 5, c4 = i & 31;
        int gn = n_base + n;
        float4 v = make_float4(0.f, 0.f, 0.f, 0.f);
        if (gn < N_NODES) v = *(const float4*)(x + (size_t)gn * 128 + c4 * 4);
        *(float4*)(xs + n * XS_STRIDE + c4 * 4) = v;
    }
    __syncthreads();

    const int warp = t >> 5;          // 0..7 -> cols warp*8..+7
    const int lane = t & 31;          // node n_base + lane
    const int c0 = warp * 8;

    float acc[8];
#pragma unroll
    for (int c = 0; c < 8; c++) acc[c] = 0.f;

    const float* xrow = xs + lane * XS_STRIDE;

#pragma unroll 2
    for (int d = 0; d < 128; d += 4) {
        const float4 xv = *(const float4*)(xrow + d);
#pragma unroll
        for (int dd = 0; dd < 4; dd++) {
            // warp-uniform broadcast loads
            const float4 wa = *(const float4*)(ws + (d + dd) * COLS_PER_CHUNK + c0);
            const float4 wb = *(const float4*)(ws + (d + dd) * COLS_PER_CHUNK + c0 + 4);
            const float xvv = ((const float*)&xv)[dd];
            acc[0] += xvv * wa.x; acc[1] += xvv * wa.y;
            acc[2] += xvv * wa.z; acc[3] += xvv * wa.w;
            acc[4] += xvv * wb.x; acc[5] += xvv * wb.y;
            acc[6] += xvv * wb.z; acc[7] += xvv * wb.w;
        }
    }

    const int node = n_base + lane;
    if (node < N_NODES) {
        float* gout = is_q ? g_q : g_k;
        float4 o0, o1;
        o0.x = acc[0] + bs[c0 + 0]; o0.y = acc[1] + bs[c0 + 1];
        o0.z = acc[2] + bs[c0 + 2]; o0.w = acc[3] + bs[c0 + 3];
        o1.x = acc[4] + bs[c0 + 4]; o1.y = acc[5] + bs[c0 + 5];
        o1.z = acc[6] + bs[c0 + 6]; o1.w = acc[7] + bs[c0 + 7];
        *(float4*)(gout + (size_t)node * 128 + wcol0 + c0) = o0;
        *(float4*)(gout + (size_t)node * 128 + wcol0 + c0 + 4) = o1;
    }
}

// ---------------- CSR build: histogram -> scan -> scatter --------------------
__global__ void hist_kernel(const int* __restrict__ etgt) {
    int i = blockIdx.x * blockDim.x + threadIdx.x;
    if (i < N_EDGES) atomicAdd(&g_count[etgt[i]], 1);
}

#define SCAN_THREADS 1024
__global__ void scan_kernel() {
    __shared__ int partial[SCAN_THREADS];
    const int t = threadIdx.x;
    const int CHUNK = (N_NODES + SCAN_THREADS - 1) / SCAN_THREADS;  // 49
    const int base = t * CHUNK;

    int s = 0;
    for (int i = 0; i < CHUNK; i++) {
        int idx = base + i;
        if (idx < N_NODES) s += g_count[idx];
    }
    partial[t] = s;
    __syncthreads();

    for (int off = 1; off < SCAN_THREADS; off <<= 1) {
        int u = (t >= off) ? partial[t - off] : 0;
        __syncthreads();
        partial[t] += u;
        __syncthreads();
    }

    int run = partial[t] - s;
    for (int i = 0; i < CHUNK; i++) {
        int idx = base + i;
        if (idx < N_NODES) {
            g_offset[idx] = run;
            g_cursor[idx] = run;
            run += g_count[idx];
        }
    }
    if (t == SCAN_THREADS - 1) g_offset[N_NODES] = partial[SCAN_THREADS - 1];
}

__global__ void scatter_kernel(const int* __restrict__ esrc,
                               const int* __restrict__ etgt) {
    int i = blockIdx.x * blockDim.x + threadIdx.x;
    if (i < N_EDGES) {
        int pos = atomicAdd(&g_cursor[etgt[i]], 1);
        g_src_sorted[pos] = esrc[i];
    }
}

// ---------------- Kernel 2: per-node gather (R6 config, MLP=4) ---------------
__global__ void __launch_bounds__(256)
gather_kernel(const float* __restrict__ attn, float* __restrict__ out) {
    __shared__ float a_s[128];
    if (threadIdx.x < 128) a_s[threadIdx.x] = attn[threadIdx.x];
    __syncthreads();

    const int node = (blockIdx.x * blockDim.x + threadIdx.x) >> 5;
    if (node >= N_NODES) return;
    const int lane = threadIdx.x & 31;
    const int part = lane & 3;
    const int h = lane >> 2;

    const float a0 = a_s[(part * 4 + 0) * 8 + h];
    const float a1 = a_s[(part * 4 + 1) * 8 + h];
    const float a2 = a_s[(part * 4 + 2) * 8 + h];
    const float a3 = a_s[(part * 4 + 3) * 8 + h];

    const float4 qv = *(const float4*)(g_q + (size_t)node * 128 + lane * 4);

    const int start = g_offset[node];
    const int end = g_offset[node + 1];

    float4 acc = make_float4(0.f, 0.f, 0.f, 0.f);
    float dsum = 0.f;

    for (int b = start; b < end; b += 32) {
        const int cnt = min(32, end - b);
        const int src_l = (lane < cnt) ? g_src_sorted[b + lane] : 0;

        int j = 0;
        for (; j + 4 <= cnt; j += 4) {
            const int s0 = __shfl_sync(0xffffffffu, src_l, j);
            const int s1 = __shfl_sync(0xffffffffu, src_l, j + 1);
            const int s2 = __shfl_sync(0xffffffffu, src_l, j + 2);
            const int s3 = __shfl_sync(0xffffffffu, src_l, j + 3);
            const float4 k0 = *(const float4*)(g_k + (size_t)s0 * 128 + lane * 4);
            const float4 k1 = *(const float4*)(g_k + (size_t)s1 * 128 + lane * 4);
            const float4 k2 = *(const float4*)(g_k + (size_t)s2 * 128 + lane * 4);
            const float4 k3 = *(const float4*)(g_k + (size_t)s3 * 128 + lane * 4);

            float p0 = lrelu(qv.x + k0.x) * a0 + lrelu(qv.y + k0.y) * a1 +
                       lrelu(qv.z + k0.z) * a2 + lrelu(qv.w + k0.w) * a3;
            float p1 = lrelu(qv.x + k1.x) * a0 + lrelu(qv.y + k1.y) * a1 +
                       lrelu(qv.z + k1.z) * a2 + lrelu(qv.w + k1.w) * a3;
            float p2 = lrelu(qv.x + k2.x) * a0 + lrelu(qv.y + k2.y) * a1 +
                       lrelu(qv.z + k2.z) * a2 + lrelu(qv.w + k2.w) * a3;
            float p3 = lrelu(qv.x + k3.x) * a0 + lrelu(qv.y + k3.y) * a1 +
                       lrelu(qv.z + k3.z) * a2 + lrelu(qv.w + k3.w) * a3;

            p0 += __shfl_xor_sync(0xffffffffu, p0, 1);
            p1 += __shfl_xor_sync(0xffffffffu, p1, 1);
            p2 += __shfl_xor_sync(0xffffffffu, p2, 1);
            p3 += __shfl_xor_sync(0xffffffffu, p3, 1);
            p0 += __shfl_xor_sync(0xffffffffu, p0, 2);
            p1 += __shfl_xor_sync(0xffffffffu, p1, 2);
            p2 += __shfl_xor_sync(0xffffffffu, p2, 2);
            p3 += __shfl_xor_sync(0xffffffffu, p3, 2);

            const float u0 = __expf(p0);
            const float u1 = __expf(p1);
            const float u2 = __expf(p2);
            const float u3 = __expf(p3);

            acc.x += u0 * k0.x + u1 * k1.x + u2 * k2.x + u3 * k3.x;
            acc.y += u0 * k0.y + u1 * k1.y + u2 * k2.y + u3 * k3.y;
            acc.z += u0 * k0.z + u1 * k1.z + u2 * k2.z + u3 * k3.z;
            acc.w += u0 * k0.w + u1 * k1.w + u2 * k2.w + u3 * k3.w;
            dsum += (u0 + u1) + (u2 + u3);
        }
        for (; j < cnt; j++) {
            const int s0 = __shfl_sync(0xffffffffu, src_l, j);
            const float4 k0 = *(const float4*)(g_k + (size_t)s0 * 128 + lane * 4);
            float p0 = lrelu(qv.x + k0.x) * a0 + lrelu(qv.y + k0.y) * a1 +
                       lrelu(qv.z + k0.z) * a2 + lrelu(qv.w + k0.w) * a3;
            p0 += __shfl_xor_sync(0xffffffffu, p0, 1);
            p0 += __shfl_xor_sync(0xffffffffu, p0, 2);
            const float u0 = __expf(p0);
            acc.x += u0 * k0.x;
            acc.y += u0 * k0.y;
            acc.z += u0 * k0.z;
            acc.w += u0 * k0.w;
            dsum += u0;
        }
    }

    const float inv = (dsum > 0.f) ? 1.f / dsum : 0.f;
    float4 o;
    o.x = fmaxf(acc.x * inv, 0.f);
    o.y = fmaxf(acc.y * inv, 0.f);
    o.z = fmaxf(acc.z * inv, 0.f);
    o.w = fmaxf(acc.w * inv, 0.f);
    *(float4*)(out + (size_t)node * 128 + lane * 4) = o;
}

// ---------------- launch ------------------------------------------------------
extern "C" void kernel_launch(void* const* d_in, const int* in_sizes, int n_in,
                              void* d_out, int out_size) {
    const float* x    = (const float*)d_in[0];
    const float* wq   = (const float*)d_in[1];
    const float* bq   = (const float*)d_in[2];
    const float* wk   = (const float*)d_in[3];
    const float* bk   = (const float*)d_in[4];
    const float* attn = (const float*)d_in[5];
    const int*   esrc = (const int*)d_in[6];
    const int*   etgt = (const int*)d_in[7];
    float* out = (float*)d_out;

    // zero the degree histogram (symbol address query, no alloc)
    void* count_ptr = nullptr;
    cudaGetSymbolAddress(&count_ptr, g_count);
    cudaMemsetAsync(count_ptr, 0, N_NODES * sizeof(int), 0);

    // CSR build
    hist_kernel<<<(N_EDGES + 255) / 256, 256>>>(etgt);
    scan_kernel<<<1, SCAN_THREADS>>>();
    scatter_kernel<<<(N_EDGES + 255) / 256, 256>>>(esrc, etgt);

    // broadcast-weight Q/K GEMM: ~48.8KB smem, 4 CTAs/SM
    static const size_t gemm_smem = (8192 + 4224 + 64) * sizeof(float);
    cudaFuncSetAttribute(qk_gemm_kernel, cudaFuncAttributeMaxDynamicSharedMemorySize,
                         (int)gemm_smem);
    dim3 gemm_grid((N_NODES + GEMM_TILE_N - 1) / GEMM_TILE_N, 4);
    qk_gemm_kernel<<<gemm_grid, GEMM_BLOCK, gemm_smem>>>(x, wq, bq, wk, bk);

    // per-node gather: one warp per node, 8 nodes per 256-thread block
    gather_kernel<<<(N_NODES * 32 + 255) / 256, 256>>>(attn, out);
}

// round 9
// speedup vs baseline: 1.1548x; 1.1548x over previous
#include <cuda_runtime.h>
#include <cuda_bf16.h>
#include <cstdint>

#define N_NODES 50000
#define N_EDGES 800000
#define D_IN 128
#define N_HEADS 8
#define PER_HEAD 16
#define LEAKY_ALPHA 0.2f

// ---------------- static device scratch (no allocations allowed) ------------
__device__ float g_q[(size_t)N_NODES * 128];         // 25.6 MB
__device__ float g_k[(size_t)N_NODES * 128];         // 25.6 MB
__device__ int   g_count[N_NODES];                   // in-degree histogram
__device__ int   g_offset[N_NODES + 1];              // CSR row offsets
__device__ int   g_cursor[N_NODES];                  // scatter cursors
__device__ int   g_src_sorted[N_EDGES];              // src node per CSR slot

__device__ __forceinline__ float lrelu(float v) {
    return v > 0.0f ? v : LEAKY_ALPHA * v;
}

// ---------------- Kernel 1: Q/K GEMM, broadcast-w + persistent blocks --------
// Warp = 8 fixed cols; lane owns 2 nodes. Per 4-d step: 2 x-LDS.128 (stride-132
// rows, bank (4l+d)%32 conflict-free) + 8 warp-uniform w-LDS.128 (broadcast,
// N=1 on the crossbar) feeding 64 FMA -> 86% FMA instruction fraction.
// Persistent node loop amortizes the 32KB weight load (R8's mistake: reloaded
// per 32-node tile -> 200MB L2 weight traffic; now 444 blocks x 32KB = 14MB).
// 256 thr, ~65.3KB smem -> 3 CTAs/SM (24 warps, the R5 sweet spot).
#define GEMM_BLOCK 256
#define GEMM_TILE_N 64
#define COLS_PER_CHUNK 64
#define XS_STRIDE 132
#define GEMM_GRID_X 111

__global__ void __launch_bounds__(GEMM_BLOCK, 3)
qk_gemm_kernel(const float* __restrict__ x,
               const float* __restrict__ wq, const float* __restrict__ bq,
               const float* __restrict__ wk, const float* __restrict__ bk) {
    extern __shared__ float smem[];
    float* ws = smem;                        // [128][64] = 8192 floats (32KB)
    float* xs = smem + 8192;                 // [64][132] = 8448 floats (33KB)
    float* bs = smem + 8192 + 8448;          // 64 floats

    const int t = threadIdx.x;
    const int col0 = blockIdx.y * COLS_PER_CHUNK;  // 0,64,128,192
    const bool is_q = (col0 < 128);
    const float* wsrc = is_q ? wq : wk;
    const float* bsrc = is_q ? bq : bk;
    const int wcol0 = is_q ? col0 : (col0 - 128);

    // load weight chunk once per block (coalesced)
    for (int i = t; i < 128 * COLS_PER_CHUNK; i += GEMM_BLOCK) {
        int d = i >> 6, c = i & 63;
        ws[i] = wsrc[d * 128 + wcol0 + c];
    }
    if (t < COLS_PER_CHUNK) bs[t] = bsrc[wcol0 + t];

    const int warp = t >> 5;          // 0..7 -> cols warp*8..+7
    const int lane = t & 31;
    const int c0 = warp * 8;
    float* gout = is_q ? g_q : g_k;

    for (int n0 = blockIdx.x * GEMM_TILE_N; n0 < N_NODES;
         n0 += gridDim.x * GEMM_TILE_N) {
        __syncthreads();
        // stage 64 nodes x 128 floats (float4-coalesced), zero-fill past end
        for (int i = t; i < GEMM_TILE_N * 32; i += GEMM_BLOCK) {
            int n = i >> 5, c4 = i & 31;
            int gn = n0 + n;
            float4 v = make_float4(0.f, 0.f, 0.f, 0.f);
            if (gn < N_NODES) v = *(const float4*)(x + (size_t)gn * 128 + c4 * 4);
            *(float4*)(xs + n * XS_STRIDE + c4 * 4) = v;
        }
        __syncthreads();

        float acc0[8], acc1[8];
#pragma unroll
        for (int c = 0; c < 8; c++) { acc0[c] = 0.f; acc1[c] = 0.f; }

        const float* xr0 = xs + lane * XS_STRIDE;
        const float* xr1 = xs + (lane + 32) * XS_STRIDE;

#pragma unroll 2
        for (int d = 0; d < 128; d += 4) {
            const float4 xv0 = *(const float4*)(xr0 + d);
            const float4 xv1 = *(const float4*)(xr1 + d);
#pragma unroll
            for (int dd = 0; dd < 4; dd++) {
                // warp-uniform broadcast loads (N=1 on the crossbar)
                const float4 wa = *(const float4*)(ws + (d + dd) * COLS_PER_CHUNK + c0);
                const float4 wb = *(const float4*)(ws + (d + dd) * COLS_PER_CHUNK + c0 + 4);
                const float x0 = ((const float*)&xv0)[dd];
                const float x1 = ((const float*)&xv1)[dd];
                acc0[0] += x0 * wa.x; acc0[1] += x0 * wa.y;
                acc0[2] += x0 * wa.z; acc0[3] += x0 * wa.w;
                acc0[4] += x0 * wb.x; acc0[5] += x0 * wb.y;
                acc0[6] += x0 * wb.z; acc0[7] += x0 * wb.w;
                acc1[0] += x1 * wa.x; acc1[1] += x1 * wa.y;
                acc1[2] += x1 * wa.z; acc1[3] += x1 * wa.w;
                acc1[4] += x1 * wb.x; acc1[5] += x1 * wb.y;
                acc1[6] += x1 * wb.z; acc1[7] += x1 * wb.w;
            }
        }

        const int nodeA = n0 + lane;
        const int nodeB = n0 + 32 + lane;
        if (nodeA < N_NODES) {
            float4 o0, o1;
            o0.x = acc0[0] + bs[c0 + 0]; o0.y = acc0[1] + bs[c0 + 1];
            o0.z = acc0[2] + bs[c0 + 2]; o0.w = acc0[3] + bs[c0 + 3];
            o1.x = acc0[4] + bs[c0 + 4]; o1.y = acc0[5] + bs[c0 + 5];
            o1.z = acc0[6] + bs[c0 + 6]; o1.w = acc0[7] + bs[c0 + 7];
            *(float4*)(gout + (size_t)nodeA * 128 + wcol0 + c0) = o0;
            *(float4*)(gout + (size_t)nodeA * 128 + wcol0 + c0 + 4) = o1;
        }
        if (nodeB < N_NODES) {
            float4 o0, o1;
            o0.x = acc1[0] + bs[c0 + 0]; o0.y = acc1[1] + bs[c0 + 1];
            o0.z = acc1[2] + bs[c0 + 2]; o0.w = acc1[3] + bs[c0 + 3];
            o1.x = acc1[4] + bs[c0 + 4]; o1.y = acc1[5] + bs[c0 + 5];
            o1.z = acc1[6] + bs[c0 + 6]; o1.w = acc1[7] + bs[c0 + 7];
            *(float4*)(gout + (size_t)nodeB * 128 + wcol0 + c0) = o0;
            *(float4*)(gout + (size_t)nodeB * 128 + wcol0 + c0 + 4) = o1;
        }
    }
}

// ---------------- CSR build: histogram -> scan -> scatter --------------------
__global__ void hist_kernel(const int* __restrict__ etgt) {
    int i = blockIdx.x * blockDim.x + threadIdx.x;
    if (i < N_EDGES) atomicAdd(&g_count[etgt[i]], 1);
}

#define SCAN_THREADS 1024
__global__ void scan_kernel() {
    __shared__ int partial[SCAN_THREADS];
    const int t = threadIdx.x;
    const int CHUNK = (N_NODES + SCAN_THREADS - 1) / SCAN_THREADS;  // 49
    const int base = t * CHUNK;

    int s = 0;
    for (int i = 0; i < CHUNK; i++) {
        int idx = base + i;
        if (idx < N_NODES) s += g_count[idx];
    }
    partial[t] = s;
    __syncthreads();

    for (int off = 1; off < SCAN_THREADS; off <<= 1) {
        int u = (t >= off) ? partial[t - off] : 0;
        __syncthreads();
        partial[t] += u;
        __syncthreads();
    }

    int run = partial[t] - s;
    for (int i = 0; i < CHUNK; i++) {
        int idx = base + i;
        if (idx < N_NODES) {
            g_offset[idx] = run;
            g_cursor[idx] = run;
            run += g_count[idx];
        }
    }
    if (t == SCAN_THREADS - 1) g_offset[N_NODES] = partial[SCAN_THREADS - 1];
}

__global__ void scatter_kernel(const int* __restrict__ esrc,
                               const int* __restrict__ etgt) {
    int i = blockIdx.x * blockDim.x + threadIdx.x;
    if (i < N_EDGES) {
        int pos = atomicAdd(&g_cursor[etgt[i]], 1);
        g_src_sorted[pos] = esrc[i];
    }
}

// ---------------- Kernel 2: per-node gather (known-good config, MLP=4) -------
__global__ void __launch_bounds__(256)
gather_kernel(const float* __restrict__ attn, float* __restrict__ out) {
    __shared__ float a_s[128];
    if (threadIdx.x < 128) a_s[threadIdx.x] = attn[threadIdx.x];
    __syncthreads();

    const int node = (blockIdx.x * blockDim.x + threadIdx.x) >> 5;
    if (node >= N_NODES) return;
    const int lane = threadIdx.x & 31;
    const int part = lane & 3;
    const int h = lane >> 2;

    const float a0 = a_s[(part * 4 + 0) * 8 + h];
    const float a1 = a_s[(part * 4 + 1) * 8 + h];
    const float a2 = a_s[(part * 4 + 2) * 8 + h];
    const float a3 = a_s[(part * 4 + 3) * 8 + h];

    const float4 qv = *(const float4*)(g_q + (size_t)node * 128 + lane * 4);

    const int start = g_offset[node];
    const int end = g_offset[node + 1];

    float4 acc = make_float4(0.f, 0.f, 0.f, 0.f);
    float dsum = 0.f;

    for (int b = start; b < end; b += 32) {
        const int cnt = min(32, end - b);
        const int src_l = (lane < cnt) ? g_src_sorted[b + lane] : 0;

        int j = 0;
        for (; j + 4 <= cnt; j += 4) {
            const int s0 = __shfl_sync(0xffffffffu, src_l, j);
            const int s1 = __shfl_sync(0xffffffffu, src_l, j + 1);
            const int s2 = __shfl_sync(0xffffffffu, src_l, j + 2);
            const int s3 = __shfl_sync(0xffffffffu, src_l, j + 3);
            const float4 k0 = *(const float4*)(g_k + (size_t)s0 * 128 + lane * 4);
            const float4 k1 = *(const float4*)(g_k + (size_t)s1 * 128 + lane * 4);
            const float4 k2 = *(const float4*)(g_k + (size_t)s2 * 128 + lane * 4);
            const float4 k3 = *(const float4*)(g_k + (size_t)s3 * 128 + lane * 4);

            float p0 = lrelu(qv.x + k0.x) * a0 + lrelu(qv.y + k0.y) * a1 +
                       lrelu(qv.z + k0.z) * a2 + lrelu(qv.w + k0.w) * a3;
            float p1 = lrelu(qv.x + k1.x) * a0 + lrelu(qv.y + k1.y) * a1 +
                       lrelu(qv.z + k1.z) * a2 + lrelu(qv.w + k1.w) * a3;
            float p2 = lrelu(qv.x + k2.x) * a0 + lrelu(qv.y + k2.y) * a1 +
                       lrelu(qv.z + k2.z) * a2 + lrelu(qv.w + k2.w) * a3;
            float p3 = lrelu(qv.x + k3.x) * a0 + lrelu(qv.y + k3.y) * a1 +
                       lrelu(qv.z + k3.z) * a2 + lrelu(qv.w + k3.w) * a3;

            p0 += __shfl_xor_sync(0xffffffffu, p0, 1);
            p1 += __shfl_xor_sync(0xffffffffu, p1, 1);
            p2 += __shfl_xor_sync(0xffffffffu, p2, 1);
            p3 += __shfl_xor_sync(0xffffffffu, p3, 1);
            p0 += __shfl_xor_sync(0xffffffffu, p0, 2);
            p1 += __shfl_xor_sync(0xffffffffu, p1, 2);
            p2 += __shfl_xor_sync(0xffffffffu, p2, 2);
            p3 += __shfl_xor_sync(0xffffffffu, p3, 2);

            const float u0 = __expf(p0);
            const float u1 = __expf(p1);
            const float u2 = __expf(p2);
            const float u3 = __expf(p3);

            acc.x += u0 * k0.x + u1 * k1.x + u2 * k2.x + u3 * k3.x;
            acc.y += u0 * k0.y + u1 * k1.y + u2 * k2.y + u3 * k3.y;
            acc.z += u0 * k0.z + u1 * k1.z + u2 * k2.z + u3 * k3.z;
            acc.w += u0 * k0.w + u1 * k1.w + u2 * k2.w + u3 * k3.w;
            dsum += (u0 + u1) + (u2 + u3);
        }
        for (; j < cnt; j++) {
            const int s0 = __shfl_sync(0xffffffffu, src_l, j);
            const float4 k0 = *(const float4*)(g_k + (size_t)s0 * 128 + lane * 4);
            float p0 = lrelu(qv.x + k0.x) * a0 + lrelu(qv.y + k0.y) * a1 +
                       lrelu(qv.z + k0.z) * a2 + lrelu(qv.w + k0.w) * a3;
            p0 += __shfl_xor_sync(0xffffffffu, p0, 1);
            p0 += __shfl_xor_sync(0xffffffffu, p0, 2);
            const float u0 = __expf(p0);
            acc.x += u0 * k0.x;
            acc.y += u0 * k0.y;
            acc.z += u0 * k0.z;
            acc.w += u0 * k0.w;
            dsum += u0;
        }
    }

    const float inv = (dsum > 0.f) ? 1.f / dsum : 0.f;
    float4 o;
    o.x = fmaxf(acc.x * inv, 0.f);
    o.y = fmaxf(acc.y * inv, 0.f);
    o.z = fmaxf(acc.z * inv, 0.f);
    o.w = fmaxf(acc.w * inv, 0.f);
    *(float4*)(out + (size_t)node * 128 + lane * 4) = o;
}

// ---------------- launch ------------------------------------------------------
extern "C" void kernel_launch(void* const* d_in, const int* in_sizes, int n_in,
                              void* d_out, int out_size) {
    const float* x    = (const float*)d_in[0];
    const float* wq   = (const float*)d_in[1];
    const float* bq   = (const float*)d_in[2];
    const float* wk   = (const float*)d_in[3];
    const float* bk   = (const float*)d_in[4];
    const float* attn = (const float*)d_in[5];
    const int*   esrc = (const int*)d_in[6];
    const int*   etgt = (const int*)d_in[7];
    float* out = (float*)d_out;

    // zero the degree histogram (symbol address query, no alloc)
    void* count_ptr = nullptr;
    cudaGetSymbolAddress(&count_ptr, g_count);
    cudaMemsetAsync(count_ptr, 0, N_NODES * sizeof(int), 0);

    // CSR build
    hist_kernel<<<(N_EDGES + 255) / 256, 256>>>(etgt);
    scan_kernel<<<1, SCAN_THREADS>>>();
    scatter_kernel<<<(N_EDGES + 255) / 256, 256>>>(esrc, etgt);

    // persistent broadcast-w Q/K GEMM: ~65.3KB smem, 3 CTAs/SM
    static const size_t gemm_smem = (8192 + 8448 + 64) * sizeof(float);
    cudaFuncSetAttribute(qk_gemm_kernel, cudaFuncAttributeMaxDynamicSharedMemorySize,
                         (int)gemm_smem);
    dim3 gemm_grid(GEMM_GRID_X, 4);
    qk_gemm_kernel<<<gemm_grid, GEMM_BLOCK, gemm_smem>>>(x, wq, bq, wk, bk);

    // per-node gather: one warp per node, 8 nodes per 256-thread block
    gather_kernel<<<(N_NODES * 32 + 255) / 256, 256>>>(attn, out);
}